// round 8
// baseline (speedup 1.0000x reference)
#include <cuda_runtime.h>

#define MAXN 100000
#define DFEAT 64

// Scratch (allocation-free): message accumulator, degree, hidden layer output.
__device__ __align__(16) float g_msg[MAXN * DFEAT];
__device__ __align__(16) float g_deg[MAXN];
__device__ __align__(16) float g_h[MAXN * DFEAT];

// ---------------------------------------------------------------------------
// Zeroing kernel (graph memset nodes reject __device__ symbol memory).
// ---------------------------------------------------------------------------
__global__ void zero_kernel(float4* __restrict__ msg, float* __restrict__ deg,
                            int n4, int ndeg) {
    int i = blockIdx.x * blockDim.x + threadIdx.x;
    if (i < n4) msg[i] = make_float4(0.f, 0.f, 0.f, 0.f);
    if (deg != nullptr && i < ndeg) deg[i] = 0.f;
}

// ---------------------------------------------------------------------------
// Scatter: for each edge (s -> d), msg[d] += feat[s]; optionally deg[d] += 1.
// 16 threads per edge, each moving one float4 (16B) with a vector atomic.
// edge indices are INT32 (JAX x64-disabled downcasts the reference's int64).
// ---------------------------------------------------------------------------
__global__ void scatter_kernel(const float* __restrict__ feat,
                               const int* __restrict__ src,
                               const int* __restrict__ dst,
                               float* __restrict__ msg,
                               float* __restrict__ deg,
                               int E) {
    int tid = blockIdx.x * blockDim.x + threadIdx.x;
    int e = tid >> 4;
    if (e >= E) return;
    int c = tid & 15;
    int s = src[e];
    int d = dst[e];
    float4 v = reinterpret_cast<const float4*>(feat)[s * 16 + c];
    atomicAdd(reinterpret_cast<float4*>(msg) + d * 16 + c, v);
    if (deg != nullptr && c == 0) atomicAdd(deg + d, 1.0f);
}

// ---------------------------------------------------------------------------
// Fused SAGE layer: out = (msg/max(deg,1)) @ Wl + bl + xin @ Wr
//   RELU: apply relu and store hidden [N,64]
//   CLS : instead of storing h2, fuse classifier out2 = h2 @ Wc + bc  [N,2]
// Block: 256 threads, 32 node-rows per block.
// Shared: Wl(16KB) + Wr(16KB) + A-tile(8KB) + X-tile(8KB) = 48KB.
// Thread tile: 4 rows x 2 cols x 2 input matrices.
// ---------------------------------------------------------------------------
template <bool RELU, bool CLS>
__global__ __launch_bounds__(256) void layer_kernel(
    const float* __restrict__ msg, const float* __restrict__ deg,
    const float* __restrict__ xin,
    const float* __restrict__ Wl, const float* __restrict__ bl,
    const float* __restrict__ Wr,
    const float* __restrict__ Wc, const float* __restrict__ bc,
    float* __restrict__ hout, float* __restrict__ out2, int N)
{
    __shared__ float sWl[64 * 64];
    __shared__ float sWr[64 * 64];
    __shared__ float sA[32 * 64];
    __shared__ float sX[32 * 64];

    int tid = threadIdx.x;

    // Load both weight matrices (row-major [k][c]) into shared.
    for (int i = tid; i < 1024; i += 256) {
        reinterpret_cast<float4*>(sWl)[i] = reinterpret_cast<const float4*>(Wl)[i];
        reinterpret_cast<float4*>(sWr)[i] = reinterpret_cast<const float4*>(Wr)[i];
    }

    int rowbase = blockIdx.x * 32;

    // Load the 32-row activation tiles; scale msg by 1/max(deg,1) on the way in.
    for (int i = tid; i < 512; i += 256) {  // 512 float4 per tile
        int r = i >> 4;
        int row = rowbase + r;
        if (row >= N) row = N - 1;
        int g = row * 16 + (i & 15);
        float4 a = reinterpret_cast<const float4*>(msg)[g];
        float inv = 1.0f / fmaxf(deg[row], 1.0f);
        a.x *= inv; a.y *= inv; a.z *= inv; a.w *= inv;
        reinterpret_cast<float4*>(sA)[i] = a;
        reinterpret_cast<float4*>(sX)[i] = reinterpret_cast<const float4*>(xin)[g];
    }
    __syncthreads();

    int tx = tid & 31;        // lane -> output columns tx, tx+32
    int ty = tid >> 5;        // warp -> rows ty*4 .. ty*4+3
    int c0 = tx, c1 = tx + 32;

    float bias0 = bl[c0], bias1 = bl[c1];
    float acc[4][2];
#pragma unroll
    for (int rr = 0; rr < 4; rr++) { acc[rr][0] = bias0; acc[rr][1] = bias1; }

#pragma unroll 4
    for (int k4 = 0; k4 < 64; k4 += 4) {
        float af[4][4], xf[4][4];
#pragma unroll
        for (int rr = 0; rr < 4; rr++) {
            *reinterpret_cast<float4*>(af[rr]) =
                *reinterpret_cast<const float4*>(&sA[(ty * 4 + rr) * 64 + k4]);
            *reinterpret_cast<float4*>(xf[rr]) =
                *reinterpret_cast<const float4*>(&sX[(ty * 4 + rr) * 64 + k4]);
        }
#pragma unroll
        for (int kk = 0; kk < 4; kk++) {
            float wl0 = sWl[(k4 + kk) * 64 + c0];
            float wl1 = sWl[(k4 + kk) * 64 + c1];
            float wr0 = sWr[(k4 + kk) * 64 + c0];
            float wr1 = sWr[(k4 + kk) * 64 + c1];
#pragma unroll
            for (int rr = 0; rr < 4; rr++) {
                acc[rr][0] += af[rr][kk] * wl0 + xf[rr][kk] * wr0;
                acc[rr][1] += af[rr][kk] * wl1 + xf[rr][kk] * wr1;
            }
        }
    }

    if (RELU) {
#pragma unroll
        for (int rr = 0; rr < 4; rr++) {
            int row = rowbase + ty * 4 + rr;
            if (row < N) {
                hout[row * 64 + c0] = fmaxf(acc[rr][0], 0.0f);
                hout[row * 64 + c1] = fmaxf(acc[rr][1], 0.0f);
            }
        }
    }
    if (CLS) {
        // Fused classifier: out[row] = h2[row] @ Wc + bc. Each thread holds
        // cols c0,c1 of h2 for 4 rows; warp shuffle-reduce across the 64 cols.
        float wc00 = Wc[c0 * 2 + 0], wc01 = Wc[c0 * 2 + 1];
        float wc10 = Wc[c1 * 2 + 0], wc11 = Wc[c1 * 2 + 1];
#pragma unroll
        for (int rr = 0; rr < 4; rr++) {
            float p0 = acc[rr][0] * wc00 + acc[rr][1] * wc10;
            float p1 = acc[rr][0] * wc01 + acc[rr][1] * wc11;
#pragma unroll
            for (int off = 16; off > 0; off >>= 1) {
                p0 += __shfl_down_sync(0xffffffffu, p0, off);
                p1 += __shfl_down_sync(0xffffffffu, p1, off);
            }
            if (tx == 0) {
                int row = rowbase + ty * 4 + rr;
                if (row < N) {
                    out2[row * 2 + 0] = p0 + bc[0];
                    out2[row * 2 + 1] = p1 + bc[1];
                }
            }
        }
    }
}

extern "C" void kernel_launch(void* const* d_in, const int* in_sizes, int n_in,
                              void* d_out, int out_size) {
    const float* x   = (const float*)d_in[0];
    const int*   ei  = (const int*)d_in[1];     // int32 (JAX x64-disabled)
    const float* W1l = (const float*)d_in[2];
    const float* b1  = (const float*)d_in[3];
    const float* W1r = (const float*)d_in[4];
    const float* W2l = (const float*)d_in[5];
    const float* b2  = (const float*)d_in[6];
    const float* W2r = (const float*)d_in[7];
    const float* Wc  = (const float*)d_in[8];
    const float* bc  = (const float*)d_in[9];
    float*       out = (float*)d_out;

    int N = in_sizes[0] / DFEAT;
    int E = in_sizes[1] / 2;
    const int* src = ei;
    const int* dst = ei + E;

    float *msg, *deg, *h;
    cudaGetSymbolAddress((void**)&msg, g_msg);
    cudaGetSymbolAddress((void**)&deg, g_deg);
    cudaGetSymbolAddress((void**)&h,   g_h);

    int n4 = N * DFEAT / 4;                 // float4 count in msg
    int zgrid = (n4 + 255) / 256;
    int sgrid = (int)(((long long)E * 16 + 255) / 256);
    int lgrid = (N + 31) / 32;

    // Layer 1
    zero_kernel<<<zgrid, 256>>>((float4*)msg, deg, n4, N);
    scatter_kernel<<<sgrid, 256>>>(x, src, dst, msg, deg, E);
    layer_kernel<true, false><<<lgrid, 256>>>(msg, deg, x, W1l, b1, W1r,
                                              nullptr, nullptr, h, nullptr, N);
    // Layer 2 (+ fused classifier); degree is reused.
    zero_kernel<<<zgrid, 256>>>((float4*)msg, nullptr, n4, 0);
    scatter_kernel<<<sgrid, 256>>>(h, src, dst, msg, nullptr, E);
    layer_kernel<false, true><<<lgrid, 256>>>(msg, deg, h, W2l, b2, W2r,
                                              Wc, bc, nullptr, out, N);
}